// round 6
// baseline (speedup 1.0000x reference)
#include <cuda_runtime.h>
#include <cuda_bf16.h>

// DTW min-plus DP, N=65536 rows (input), K=512 cols (kernel).
// ac[i][j] = min(ac[i-1][j-1], ac[i-1][j], ac[i][j-1]) + (kernel[j]-input[i])^2
// boundary: row -1 and col -1 = +inf, except diag for (0,0) = 0.
// Output: ac[i][K-1] for all i.
//
// Band-rotation wavefront: thread p owns tile-rows m = p + 512*b (R=32 rows each),
// sweeping columns 0..511 over consecutive supersteps. The 32 "left" values stay
// in the thread's registers; the single up-carry scalar moves thread p-1 -> p
// via one shfl per superstep (smem word at warp boundaries, ring warp15->warp0).

#define NROWS 65536
#define KCOLS 512
#define RB    32            // rows per band
#define NBANDS (NROWS / RB) // 2048
#define NTHREADS 512
#define NSTEPS (NBANDS + NTHREADS - 1) // 2559 supersteps

__global__ void __launch_bounds__(512, 1)
dtw_band_kernel(const float* __restrict__ x, const float* __restrict__ ker,
                float* __restrict__ out)
{
    __shared__ float sk[KCOLS];
    __shared__ float sbuf[2][16];   // [parity][producer warp] up-carry handoff

    const int p    = threadIdx.x;
    const int lane = p & 31;
    const int warp = p >> 5;
    const float INF = __int_as_float(0x7f800000);

    sk[p] = ker[p];
    __syncthreads();

    float V[RB];    // current column's ac values for my band (also "left" for next col)
    float xv[RB];   // my band's input values
    float diagc = INF;   // ac[i0-1][j-1] carry
    float alast = INF;   // my last-row ac from previous superstep (feeds neighbor's up-carry)

    int phase = -p;      // = t - p; band = phase>>9, column j = phase & 511

    for (int t = 0; t < NSTEPS; ++t, ++phase) {
        // neighbor's alast as of end of superstep t-1 (same (band, j) as me-now, m-1)
        float nb = __shfl_up_sync(0xffffffffu, alast, 1);
        if (lane == 0) nb = sbuf[t & 1][(warp + 15) & 15];

        if (phase >= 0 && phase < NBANDS) {
            const int j = phase & (KCOLS - 1);
            if (j == 0) {
                // band start: load my 32 input values, reset left column to +inf
                const int i0 = (p << 5) + ((phase >> 9) << 14); // (p + 512*band)*32
                const float4* xp = reinterpret_cast<const float4*>(x + i0);
#pragma unroll
                for (int q = 0; q < RB / 4; ++q) {
                    float4 v = xp[q];
                    xv[4 * q + 0] = v.x; xv[4 * q + 1] = v.y;
                    xv[4 * q + 2] = v.z; xv[4 * q + 3] = v.w;
                }
#pragma unroll
                for (int r = 0; r < RB; ++r) V[r] = INF;
                diagc = INF;
                if (p == 0 && t == 0) diagc = 0.0f;  // virtual diag for cell (0,0)
            }

            // up-carry: ac[i0-1][j]; +inf for the very first band (m == 0)
            const float upv = (p == 0 && phase < KCOLS) ? INF : nb;
            const float kj  = sk[j];

            float a     = upv;    // running chain = "up" entering row r
            float prevL = diagc;  // diag for r==0
#pragma unroll
            for (int r = 0; r < RB; ++r) {
                const float curL = V[r];            // left: ac[i0+r][j-1]
                const float u    = kj - xv[r];
                a = fminf(a, fminf(curL, prevL));   // min(up, left, diag)
                a = fmaf(u, u, a);                  // + d
                prevL = curL;
                V[r] = a;
            }
            diagc = upv;   // diag for (i0, j+1) is ac[i0-1][j]
            alast = a;

            if (j == KCOLS - 1) {
                const int i0 = (p << 5) + ((phase >> 9) << 14);
                float4* op = reinterpret_cast<float4*>(out + i0);
#pragma unroll
                for (int q = 0; q < RB / 4; ++q)
                    op[q] = make_float4(V[4 * q + 0], V[4 * q + 1],
                                        V[4 * q + 2], V[4 * q + 3]);
            }
        }

        if (lane == 31) sbuf[(t + 1) & 1][warp] = alast;
        __syncthreads();
    }
}

extern "C" void kernel_launch(void* const* d_in, const int* in_sizes, int n_in,
                              void* d_out, int out_size)
{
    const float* x   = (const float*)d_in[0];   // input, 65536
    const float* ker = (const float*)d_in[1];   // kernel, 512
    float* out = (float*)d_out;                 // 65536
    (void)in_sizes; (void)n_in; (void)out_size;
    dtw_band_kernel<<<1, NTHREADS>>>(x, ker, out);
}